// round 6
// baseline (speedup 1.0000x reference)
#include <cuda_runtime.h>
#include <cuda_fp16.h>
#include <cstdint>

#define BSZ 32
#define NP  64
#define NN  (NP*NP)   // 4096

typedef unsigned long long u64;

// ---------------- device scratch ----------------
__device__ float g_att[6 * BSZ * NN];     // attq1, attq2, attq3, Tjk, Tjl, Akl (pre-scaled 0.0625)
__device__ float g_anchor2[2 * BSZ * NP]; // per (k-half, b, i) partial sums

// ---------------- f32x2 packed helpers ----------------
__device__ __forceinline__ u64 pk2(float lo, float hi) {
    u64 r; asm("mov.b64 %0,{%1,%2};" : "=l"(r) : "f"(lo), "f"(hi)); return r;
}
__device__ __forceinline__ void upk2(float& lo, float& hi, u64 v) {
    asm("mov.b64 {%0,%1},%2;" : "=f"(lo), "=f"(hi) : "l"(v));
}
__device__ __forceinline__ u64 dup2(float x) { return pk2(x, x); }
__device__ __forceinline__ u64 add2(u64 a, u64 b) {
    u64 r; asm("add.rn.f32x2 %0,%1,%2;" : "=l"(r) : "l"(a), "l"(b)); return r;
}
__device__ __forceinline__ u64 mul2(u64 a, u64 b) {
    u64 r; asm("mul.rn.f32x2 %0,%1,%2;" : "=l"(r) : "l"(a), "l"(b)); return r;
}
__device__ __forceinline__ u64 fma2(u64 a, u64 b, u64 c) {
    u64 r; asm("fma.rn.f32x2 %0,%1,%2,%3;" : "=l"(r) : "l"(a), "l"(b), "l"(c)); return r;
}

// f16x2 gate: sigma = 0.5 + 0.5*tanh(z), two z's per MUFU instruction.
// In: packed f32x2 energies. Out: packed f32x2 gates.
__device__ __forceinline__ u64 gate2_f16(u64 e2) {
    float elo, ehi; upk2(elo, ehi, e2);
    uint32_t eh, th, gh;
    asm("cvt.rn.f16x2.f32 %0,%1,%2;" : "=r"(eh) : "f"(ehi), "f"(elo));  // h1=ehi,h0=elo
    asm("tanh.approx.f16x2 %0,%1;" : "=r"(th) : "r"(eh));
    asm("fma.rn.f16x2 %0,%1,%2,%2;" : "=r"(gh) : "r"(th), "r"(0x38003800u)); // 0.5*t+0.5
    float glo, ghi;
    asm("{ .reg .b16 l,h; mov.b32 {l,h},%2; cvt.f32.f16 %0,l; cvt.f32.f16 %1,h; }"
        : "=f"(glo), "=f"(ghi) : "r"(gh));
    return pk2(glo, ghi);
}

// ---------------- k12: fused dense + six N x N attention matrices ----------------
// out[r*64+c] = 0.0625 * dot(S1[c,:], S2[r,:])
// m0: attq1[i][j] (S1=K1,S2=Q)   m3: Tjk[k][j] (S1=K1,S2=K2)
// m1: attq2[i][k] (S1=K2,S2=Q)   m4: Tjl[l][j] (S1=K1,S2=K3)
// m2: attq3[i][l] (S1=K3,S2=Q)   m5: Akl[k][l] (S1=K3,S2=K2)
__global__ void k12_att(const float* __restrict__ pts,
                        const float* __restrict__ Wq,  const float* __restrict__ bq,
                        const float* __restrict__ Wk1, const float* __restrict__ bk1,
                        const float* __restrict__ Wk2, const float* __restrict__ bk2,
                        const float* __restrict__ Wk3, const float* __restrict__ bk3) {
    __shared__ float S1t[64 * 65];
    __shared__ float S2s[64 * 64];
    int blk = blockIdx.x;
    int b = blk / 6, m = blk % 6;
    const int s1tab[6] = {1, 2, 3, 1, 1, 3};
    const int s2tab[6] = {0, 0, 0, 2, 3, 2};
    int s1 = s1tab[m], s2 = s2tab[m];
    const float* WA; const float* bA;
    const float* WB; const float* bB;
    if      (s1 == 1) { WA = Wk1; bA = bk1; }
    else if (s1 == 2) { WA = Wk2; bA = bk2; }
    else              { WA = Wk3; bA = bk3; }
    if      (s2 == 0) { WB = Wq;  bB = bq;  }
    else if (s2 == 2) { WB = Wk2; bB = bk2; }
    else              { WB = Wk3; bB = bk3; }
    for (int t = threadIdx.x; t < NN; t += blockDim.x) {
        int n = t >> 6, d = t & 63;
        const float* p = pts + (b * NP + n) * 3;
        float v1 = fmaf(p[0], WA[d], fmaf(p[1], WA[64 + d], fmaf(p[2], WA[128 + d], bA[d])));
        float v2 = fmaf(p[0], WB[d], fmaf(p[1], WB[64 + d], fmaf(p[2], WB[128 + d], bB[d])));
        S1t[d * 65 + n] = v1;
        S2s[n * 64 + d] = v2;
    }
    __syncthreads();
    const float cscale = 0.0625f;
    for (int e = threadIdx.x; e < NN; e += blockDim.x) {
        int r = e >> 6, c = e & 63;
        float acc = 0.f;
        #pragma unroll
        for (int d = 0; d < 64; d++)
            acc = fmaf(S1t[d * 65 + c], S2s[r * 64 + d], acc);
        g_att[(m * BSZ + b) * NN + e] = acc * cscale;
    }
}

// ---------------- pad: keeps ncu's capture slot on k3 ----------------
__global__ void k_pad() {}

// ---------------- k3: 537M-eval gated-det core ----------------
// grid 4096 = B(32) x anchors(64) x k-halves(2); block 128 (4 warps).
// Warp owns 8 k's; per t4-iter each lane handles k_a and k_b=k_a+4,
// with the (l=lane, l+32) pair packed in f32x2 -> 4 evals/lane/j.
// Gate via tanh.approx.f16x2: ONE MUFU instruction per 2 packed evals.
__global__ void __launch_bounds__(128, 8) k3_core(const float* __restrict__ pts) {
    __shared__ ulonglong2 JXY_s[64];     // ((x,x),(y,y)) pairs, LDS.128 bcast  1KB
    __shared__ u64    JZ2_s[64];         // (z,z) pairs  0.5KB
    __shared__ u64    T2_s[4 * 4 * 64];  // [(w*4+t4)*64+j] = (Tjk[ka][j], Tjk[kb][j])  8KB
    __shared__ u64    P2_s[64 * 32];     // [j][lane] = {P(l,j), P(l+32,j)}  16KB
    __shared__ float4 D4_s[64];          // raw disp  1KB
    __shared__ float  red_s[4];

    int bx = blockIdx.x;
    int h  = bx & 1;
    int i  = (bx >> 1) & 63;
    int b  = bx >> 7;
    int k0 = h * 32;
    int tid = threadIdx.x, warp = tid >> 5, lane = tid & 31;

    const float* attq1 = g_att + (0 * BSZ + b) * NN;
    const float* attq2 = g_att + (1 * BSZ + b) * NN;
    const float* attq3 = g_att + (2 * BSZ + b) * NN;
    const float* Tjk   = g_att + (3 * BSZ + b) * NN;
    const float* Tjl   = g_att + (4 * BSZ + b) * NN;
    const float* Akl   = g_att + (5 * BSZ + b) * NN;

    // ---- prep ----
    {
        const float* pi = pts + (b * NP + i) * 3;
        float pix = pi[0], piy = pi[1], piz = pi[2];
        if (tid < 64) {
            const float* pp = pts + (b * NP + tid) * 3;
            float dx = pp[0] - pix, dy = pp[1] - piy, dz = pp[2] - piz;
            D4_s[tid]  = make_float4(dx, dy, dz, 0.f);
            ulonglong2 v; v.x = pk2(dx, dx); v.y = pk2(dy, dy);
            JXY_s[tid] = v;
            JZ2_s[tid] = pk2(dz, dz);
        }
    }
    for (int idx = tid; idx < 1024; idx += 128) {       // Tjk (ka,kb) pairs
        int w = idx >> 8, r = idx & 255;
        int t = r >> 6,   j = r & 63;
        int ka = k0 + 8 * w + t;
        T2_s[idx] = pk2(Tjk[ka * 64 + j], Tjk[(ka + 4) * 64 + j]);
    }
    for (int t = tid; t < 2048; t += 128) {             // fused P pairs
        int lp = t & 31, j = t >> 5;
        float a1j = attq1[i * 64 + j];
        float lo = Tjl[lp * 64 + j]        + a1j + attq3[i * 64 + lp];
        float hi = Tjl[(lp + 32) * 64 + j] + a1j + attq3[i * 64 + lp + 32];
        P2_s[j * 32 + lp] = pk2(lo, hi);
    }
    __syncthreads();

    // per-lane packed dl for (l=lane, l+32) — loop-invariant
    float4 da = D4_s[lane], db = D4_s[lane + 32];
    u64 dlx2 = pk2(da.x, db.x);
    u64 dly2 = pk2(da.y, db.y);
    u64 dlz2 = pk2(da.z, db.z);
    u64 acca = pk2(0.f, 0.f);
    u64 accb = pk2(0.f, 0.f);

    #pragma unroll 1
    for (int t4 = 0; t4 < 4; t4++) {
        int ka = k0 + 8 * warp + t4;             // uniform within warp
        int kb = ka + 4;
        float4 dka = D4_s[ka];
        float4 dkb = D4_s[kb];
        float aika = __ldg(attq2 + i * 64 + ka);
        float aikb = __ldg(attq2 + i * 64 + kb);
        u64 base2a = pk2(aika + __ldg(Akl + ka * 64 + lane),
                         aika + __ldg(Akl + ka * 64 + lane + 32));
        u64 base2b = pk2(aikb + __ldg(Akl + kb * 64 + lane),
                         aikb + __ldg(Akl + kb * 64 + lane + 32));
        u64 cxa2 = fma2(dup2(dka.y), dlz2, mul2(dup2(-dka.z), dly2));
        u64 cya2 = fma2(dup2(dka.z), dlx2, mul2(dup2(-dka.x), dlz2));
        u64 cza2 = fma2(dup2(dka.x), dly2, mul2(dup2(-dka.y), dlx2));
        u64 cxb2 = fma2(dup2(dkb.y), dlz2, mul2(dup2(-dkb.z), dly2));
        u64 cyb2 = fma2(dup2(dkb.z), dlx2, mul2(dup2(-dkb.x), dlz2));
        u64 czb2 = fma2(dup2(dkb.x), dly2, mul2(dup2(-dkb.y), dlx2));
        const u64* Trow = T2_s + (warp * 4 + t4) * 64;

        #pragma unroll 8
        for (int j = 0; j < 64; j++) {
            ulonglong2 jv = JXY_s[j];              // LDS.128 bcast: jx2, jy2
            u64 jz2 = JZ2_s[j];                    // LDS.64 bcast
            u64 tt  = Trow[j];                     // LDS.64 bcast (tka,tkb)
            u64 p2  = P2_s[j * 32 + lane];         // LDS.64 per-lane
            float tka, tkb; upk2(tka, tkb, tt);
            u64 ea2 = add2(p2, add2(dup2(tka), base2a));
            u64 eb2 = add2(p2, add2(dup2(tkb), base2b));
            u64 g2a = gate2_f16(ea2);              // 1 MUFU per 2 evals
            u64 g2b = gate2_f16(eb2);
            u64 deta = fma2(jv.x, cxa2, fma2(jv.y, cya2, mul2(jz2, cza2)));
            u64 detb = fma2(jv.x, cxb2, fma2(jv.y, cyb2, mul2(jz2, czb2)));
            u64 d2a = mul2(deta, deta);
            u64 d2b = mul2(detb, detb);
            acca = fma2(d2a, g2a, acca);           // independent chains
            accb = fma2(d2b, g2b, accb);
        }
    }

    // ---- reduction ----
    u64 acc2 = add2(acca, accb);
    float alo, ahi; upk2(alo, ahi, acc2);
    float acc = alo + ahi;
    #pragma unroll
    for (int o = 16; o; o >>= 1) acc += __shfl_down_sync(0xffffffffu, acc, o);
    if (lane == 0) red_s[warp] = acc;
    __syncthreads();
    if (tid == 0) {
        float s = red_s[0] + red_s[1] + red_s[2] + red_s[3];
        g_anchor2[h * BSZ * NP + b * NP + i] = s;
    }
}

// ---------------- k4: pooled -> gelu MLP head (warp per batch) ----------------
__global__ void k4_head(const float* __restrict__ W1, const float* __restrict__ b1,
                        const float* __restrict__ W2, const float* __restrict__ b2,
                        float* __restrict__ out) {
    int warp = threadIdx.x >> 5, lane = threadIdx.x & 31;
    int b = warp;
    float s = g_anchor2[b * 64 + lane] + g_anchor2[b * 64 + lane + 32]
            + g_anchor2[BSZ * NP + b * 64 + lane] + g_anchor2[BSZ * NP + b * 64 + lane + 32];
    #pragma unroll
    for (int o = 16; o; o >>= 1) s += __shfl_xor_sync(0xffffffffu, s, o);
    float pooled = s * (1.f / 16777216.f);         // / (N^3 * N)
    float x  = fmaf(pooled, W1[lane], b1[lane]);   // lane = hidden unit
    float x3 = x * x * x;
    float t  = tanhf(0.7978845608028654f * fmaf(0.044715f, x3, x));
    float hc = 0.5f * x * (1.f + t);               // tanh-approx gelu
    float y  = hc * W2[lane];
    #pragma unroll
    for (int o = 16; o; o >>= 1) y += __shfl_xor_sync(0xffffffffu, y, o);
    if (lane == 0) out[b] = y + b2[0];
}

// ---------------- launch ----------------
extern "C" void kernel_launch(void* const* d_in, const int* in_sizes, int n_in,
                              void* d_out, int out_size) {
    const float* pts = (const float*)d_in[0];
    const float* Wq  = (const float*)d_in[1];
    const float* bq  = (const float*)d_in[2];
    const float* Wk1 = (const float*)d_in[3];
    const float* bk1 = (const float*)d_in[4];
    const float* Wk2 = (const float*)d_in[5];
    const float* bk2 = (const float*)d_in[6];
    const float* Wk3 = (const float*)d_in[7];
    const float* bk3 = (const float*)d_in[8];
    const float* W1  = (const float*)d_in[9];
    const float* b1  = (const float*)d_in[10];
    const float* W2  = (const float*)d_in[11];
    const float* b2  = (const float*)d_in[12];
    float* out = (float*)d_out;

    k12_att<<<BSZ * 6, 256>>>(pts, Wq, bq, Wk1, bk1, Wk2, bk2, Wk3, bk3);
    k_pad<<<1, 32>>>();                       // keeps ncu capture slot on k3
    k3_core<<<BSZ * NP * 2, 128>>>(pts);
    k4_head<<<1, BSZ * 32>>>(W1, b1, W2, b2, out);
}